// round 5
// baseline (speedup 1.0000x reference)
#include <cuda_runtime.h>
#include <cstdint>
#include <cstddef>

// Problem constants
#define HID    512
#define NOBJC  151
#define NRELC  51
#define POOL   4096

// Shared-memory strides (in 32-bit words), padded for conflict-free MMA fragment loads
#define ASTR 36    // A tile: [128][36]   (bank = 4*(lane/4) + lane%4 -> conflict-free)
#define BSTR 136   // B tile: [32][136]   (bank = 8*(lane%4) + lane/4 -> conflict-free)
#define VSTR 132   // V tile: [128][132]
#define WSTR 72    // Wrel tile: [128][72]

#define K1_SMEM ((2*128*ASTR + 2*32*BSTR) * 4)
#define K2_SMEM ((2*128*ASTR + 2*32*BSTR + 128*VSTR + 128*WSTR + 3*128) * 4)

// Materialized edge_rep (8192 x 1024 fp32, 32 MB -> L2-resident for the gathers)
__device__ float g_edge_rep[(size_t)8192 * 1024];

__device__ __forceinline__ unsigned f2tf(float f) {
    unsigned u;
    asm("cvt.rna.tf32.f32 %0, %1;" : "=r"(u) : "f"(f));
    return u;
}

__device__ __forceinline__ void mma8(float (&d)[4], const unsigned (&a)[4], const unsigned (&b)[2]) {
    asm volatile(
        "mma.sync.aligned.m16n8k8.row.col.f32.tf32.tf32.f32 "
        "{%0,%1,%2,%3},{%4,%5,%6,%7},{%8,%9},{%0,%1,%2,%3};\n"
        : "+f"(d[0]), "+f"(d[1]), "+f"(d[2]), "+f"(d[3])
        : "r"(a[0]), "r"(a[1]), "r"(a[2]), "r"(a[3]), "r"(b[0]), "r"(b[1]));
}

// ---- staging: gmem(float4) -> regs, regs -> smem (cvt to tf32) -------------

__device__ __forceinline__ void stA(unsigned* __restrict__ Ab, const float4 (&ra)[4], int tid) {
#pragma unroll
    for (int i = 0; i < 4; i++) {
        int s = tid + i * 256, r = s >> 3, kq = s & 7;
        unsigned* p = Ab + r * ASTR + kq * 4;
        p[0] = f2tf(ra[i].x); p[1] = f2tf(ra[i].y); p[2] = f2tf(ra[i].z); p[3] = f2tf(ra[i].w);
    }
}
__device__ __forceinline__ void stB(unsigned* __restrict__ Bb, const float4 (&rb)[4], int tid) {
#pragma unroll
    for (int i = 0; i < 4; i++) {
        int s = tid + i * 256, kk = s >> 5, cq = s & 31;
        unsigned* p = Bb + kk * BSTR + cq * 4;
        p[0] = f2tf(rb[i].x); p[1] = f2tf(rb[i].y); p[2] = f2tf(rb[i].z); p[3] = f2tf(rb[i].w);
    }
}

// Gathered A load for K2: prod_rep[i,k] = edge_rep[k<512 ? p0 : p1][k]
__device__ __forceinline__ void ldA_g(float4 (&ra)[4], const float* __restrict__ er,
                                      const int* __restrict__ rows, int k0, int tid) {
#pragma unroll
    for (int i = 0; i < 4; i++) {
        int s = tid + i * 256, r = s >> 3, kq = s & 7;
        ra[i] = __ldg((const float4*)(er + (size_t)rows[r] * 1024 + k0 + kq * 4));
    }
}
__device__ __forceinline__ void ldB_main(float4 (&rb)[4], const float* __restrict__ Wpc,
                                         int n0, int k0, int tid) {
#pragma unroll
    for (int i = 0; i < 4; i++) {
        int s = tid + i * 256, kk = s >> 5, cq = s & 31;
        rb[i] = __ldg((const float4*)(Wpc + (size_t)(k0 + kk) * POOL + n0 + cq * 4));
    }
}
// Virtual tile 32: B = W_ctx (1024 x 51) zero-padded to 128 cols
__device__ __forceinline__ void ldB_ctx(float4 (&rb)[4], const float* __restrict__ Wctx,
                                        int k0, int tid) {
#pragma unroll
    for (int i = 0; i < 4; i++) {
        int s = tid + i * 256, kk = s >> 5, cq = s & 31, cb = cq * 4;
        const float* w = Wctx + (size_t)(k0 + kk) * NRELC;
        rb[i].x = (cb + 0 < NRELC) ? __ldg(w + cb + 0) : 0.f;
        rb[i].y = (cb + 1 < NRELC) ? __ldg(w + cb + 1) : 0.f;
        rb[i].z = (cb + 2 < NRELC) ? __ldg(w + cb + 2) : 0.f;
        rb[i].w = (cb + 3 < NRELC) ? __ldg(w + cb + 3) : 0.f;
    }
}

// One BK=32 compute step: 4 k-substeps of m16n8k8, warp tile 64x32 (2x4 warp grid)
__device__ __forceinline__ void mma_tile(float (&acc)[4][4][4], const unsigned* __restrict__ Ab,
                                         const unsigned* __restrict__ Bb, int wr, int wc, int lane) {
#pragma unroll
    for (int ks = 0; ks < 4; ks++) {
        unsigned af[4][4], bf[4][2];
#pragma unroll
        for (int tm = 0; tm < 4; tm++) {
            const unsigned* p = Ab + (wr * 64 + tm * 16 + (lane >> 2)) * ASTR + ks * 8 + (lane & 3);
            af[tm][0] = p[0];
            af[tm][1] = p[8 * ASTR];
            af[tm][2] = p[4];
            af[tm][3] = p[8 * ASTR + 4];
        }
#pragma unroll
        for (int tn = 0; tn < 4; tn++) {
            const unsigned* p = Bb + (ks * 8 + (lane & 3)) * BSTR + wc * 32 + tn * 8 + (lane >> 2);
            bf[tn][0] = p[0];
            bf[tn][1] = p[4 * BSTR];
        }
#pragma unroll
        for (int tm = 0; tm < 4; tm++)
#pragma unroll
            for (int tn = 0; tn < 4; tn++)
                mma8(acc[tm][tn], af[tm], bf[tn]);
    }
}

// ============================================================================
// Kernel 1: edge_rep = edge_ctx(8192x512) @ W_post_emb(512x1024) + b  (tf32 MMA)
// ============================================================================
__global__ void __launch_bounds__(256, 1) k1_edge_rep(
    const float* __restrict__ A, const float* __restrict__ B, const float* __restrict__ bias) {
    extern __shared__ unsigned sm1[];
    unsigned* As = sm1;
    unsigned* Bs = sm1 + 2 * 128 * ASTR;
    const int tid = threadIdx.x, lane = tid & 31, wid = tid >> 5;
    const int wr = wid >> 2, wc = wid & 3;
    const int m0 = blockIdx.x * 128, n0 = blockIdx.y * 128;

    float acc[4][4][4];
#pragma unroll
    for (int a = 0; a < 4; a++)
#pragma unroll
        for (int b = 0; b < 4; b++)
#pragma unroll
            for (int c = 0; c < 4; c++) acc[a][b][c] = 0.f;

    float4 ra[4], rb[4];
#pragma unroll
    for (int i = 0; i < 4; i++) {
        int s = tid + i * 256;
        { int r = s >> 3, kq = s & 7;
          ra[i] = __ldg((const float4*)(A + (size_t)(m0 + r) * HID + kq * 4)); }
        { int kk = s >> 5, cq = s & 31;
          rb[i] = __ldg((const float4*)(B + (size_t)kk * 1024 + n0 + cq * 4)); }
    }
    stA(As, ra, tid);
    stB(Bs, rb, tid);
    __syncthreads();

    int buf = 0;
    for (int kt = 0; kt < 16; kt++) {
        if (kt < 15) {
            int k0 = (kt + 1) * 32;
#pragma unroll
            for (int i = 0; i < 4; i++) {
                int s = tid + i * 256;
                { int r = s >> 3, kq = s & 7;
                  ra[i] = __ldg((const float4*)(A + (size_t)(m0 + r) * HID + k0 + kq * 4)); }
                { int kk = s >> 5, cq = s & 31;
                  rb[i] = __ldg((const float4*)(B + (size_t)(k0 + kk) * 1024 + n0 + cq * 4)); }
            }
        }
        mma_tile(acc, As + buf * 128 * ASTR, Bs + buf * 32 * BSTR, wr, wc, lane);
        if (kt < 15) {
            stA(As + (buf ^ 1) * 128 * ASTR, ra, tid);
            stB(Bs + (buf ^ 1) * 32 * BSTR, rb, tid);
        }
        __syncthreads();
        buf ^= 1;
    }

#pragma unroll
    for (int tm = 0; tm < 4; tm++) {
        int r = m0 + wr * 64 + tm * 16 + (lane >> 2);
#pragma unroll
        for (int tn = 0; tn < 4; tn++) {
            int c = n0 + wc * 32 + tn * 8 + 2 * (lane & 3);
            float2 bb = *(const float2*)(bias + c);
            float2 v0 = make_float2(acc[tm][tn][0] + bb.x, acc[tm][tn][1] + bb.y);
            float2 v1 = make_float2(acc[tm][tn][2] + bb.x, acc[tm][tn][3] + bb.y);
            *(float2*)(g_edge_rep + (size_t)r * 1024 + c) = v0;
            *(float2*)(g_edge_rep + (size_t)(r + 8) * 1024 + c) = v1;
        }
    }
}

// ============================================================================
// Kernel 2: fused  gather -> (prod@Wpc+b) * U -> @Wrel  (+ prod@Wctx via the
// 33rd "virtual" n-tile with identity contraction) -> + biases + freq lookup
// One CTA = 128 relation rows. Grid = 512.
// ============================================================================
__global__ void __launch_bounds__(256, 1) k2_main(
    const int* __restrict__ pair_idx, const int* __restrict__ obj_preds,
    const float* __restrict__ U,
    const float* __restrict__ Wpc, const float* __restrict__ bpc,
    const float* __restrict__ Wrel, const float* __restrict__ brel,
    const float* __restrict__ Wctx, const float* __restrict__ bctx,
    const float* __restrict__ freq, float* __restrict__ out) {
    extern __shared__ unsigned sm2[];
    unsigned* As = sm2;                      // [2][128][ASTR]
    unsigned* Bs = As + 2 * 128 * ASTR;      // [2][32][BSTR]
    unsigned* Vs = Bs + 2 * 32 * BSTR;       // [128][VSTR]
    unsigned* Ws = Vs + 128 * VSTR;          // [128][WSTR]
    int* rows0 = (int*)(Ws + 128 * WSTR);
    int* rows1 = rows0 + 128;
    int* pp    = rows1 + 128;

    const float* er = g_edge_rep;
    const int tid = threadIdx.x, lane = tid & 31, wid = tid >> 5;
    const int wr = wid >> 2, wc = wid & 3;
    const int m0 = blockIdx.x * 128;

    if (tid < 128) {
        int i = m0 + tid;
        int p0 = pair_idx[2 * i], p1 = pair_idx[2 * i + 1];
        rows0[tid] = p0;
        rows1[tid] = p1;
        pp[tid] = obj_preds[p0] * NOBJC + obj_preds[p1];
    }
    __syncthreads();

    // Persistent output accumulator: 128x64 tile, warp tile 64x16 (2x4 warp grid)
    float acc2[4][2][4];
#pragma unroll
    for (int a = 0; a < 4; a++)
#pragma unroll
        for (int b = 0; b < 2; b++)
#pragma unroll
            for (int c = 0; c < 4; c++) acc2[a][b][c] = 0.f;

    float4 ra[4], rb[4];

    for (int nt = 0; nt < 33; nt++) {
        const int n0 = nt * 128;

        float acc[4][4][4];
#pragma unroll
        for (int a = 0; a < 4; a++)
#pragma unroll
            for (int b = 0; b < 4; b++)
#pragma unroll
                for (int c = 0; c < 4; c++) acc[a][b][c] = 0.f;

        // ---- G = prod_rep_tile @ B_tile  (K = 1024, BK = 32, double-buffered) ----
        ldA_g(ra, er, rows0, 0, tid);
        if (nt < 32) ldB_main(rb, Wpc, n0, 0, tid);
        else         ldB_ctx(rb, Wctx, 0, tid);
        stA(As, ra, tid);
        stB(Bs, rb, tid);
        __syncthreads();

        int buf = 0;
        for (int kt = 0; kt < 32; kt++) {
            if (kt < 31) {
                int k0 = (kt + 1) * 32;
                ldA_g(ra, er, (k0 < HID) ? rows0 : rows1, k0, tid);
                if (nt < 32) ldB_main(rb, Wpc, n0, k0, tid);
                else         ldB_ctx(rb, Wctx, k0, tid);
            }
            mma_tile(acc, As + buf * 128 * ASTR, Bs + buf * 32 * BSTR, wr, wc, lane);
            if (kt < 31) {
                stA(As + (buf ^ 1) * 128 * ASTR, ra, tid);
                stB(Bs + (buf ^ 1) * 32 * BSTR, rb, tid);
            }
            __syncthreads();
            buf ^= 1;
        }

        // ---- V = (G + b_post_cat) * U  (or V = G for the virtual ctx tile) -> smem
        //      and load the Wrel chunk (or identity) ----
        if (nt < 32) {
#pragma unroll
            for (int tm = 0; tm < 4; tm++) {
                int rl = wr * 64 + tm * 16 + (lane >> 2);
                const float* u0p = U + (size_t)(m0 + rl) * POOL + n0;
                const float* u1p = U + (size_t)(m0 + rl + 8) * POOL + n0;
#pragma unroll
                for (int tn = 0; tn < 4; tn++) {
                    int cl = wc * 32 + tn * 8 + 2 * (lane & 3);
                    float2 bb = *(const float2*)(bpc + n0 + cl);
                    float2 u0 = __ldg((const float2*)(u0p + cl));
                    float2 u1 = __ldg((const float2*)(u1p + cl));
                    Vs[rl * VSTR + cl]           = f2tf((acc[tm][tn][0] + bb.x) * u0.x);
                    Vs[rl * VSTR + cl + 1]       = f2tf((acc[tm][tn][1] + bb.y) * u0.y);
                    Vs[(rl + 8) * VSTR + cl]     = f2tf((acc[tm][tn][2] + bb.x) * u1.x);
                    Vs[(rl + 8) * VSTR + cl + 1] = f2tf((acc[tm][tn][3] + bb.y) * u1.y);
                }
            }
#pragma unroll 4
            for (int i = 0; i < 32; i++) {
                int s = tid + i * 256, nn = s >> 6, c = s & 63;
                float v = (c < NRELC) ? __ldg(Wrel + (size_t)(n0 + nn) * NRELC + c) : 0.f;
                Ws[nn * WSTR + c] = f2tf(v);
            }
        } else {
#pragma unroll
            for (int tm = 0; tm < 4; tm++) {
                int rl = wr * 64 + tm * 16 + (lane >> 2);
#pragma unroll
                for (int tn = 0; tn < 4; tn++) {
                    int cl = wc * 32 + tn * 8 + 2 * (lane & 3);
                    Vs[rl * VSTR + cl]           = f2tf(acc[tm][tn][0]);
                    Vs[rl * VSTR + cl + 1]       = f2tf(acc[tm][tn][1]);
                    Vs[(rl + 8) * VSTR + cl]     = f2tf(acc[tm][tn][2]);
                    Vs[(rl + 8) * VSTR + cl + 1] = f2tf(acc[tm][tn][3]);
                }
            }
#pragma unroll 4
            for (int i = 0; i < 32; i++) {
                int s = tid + i * 256, nn = s >> 6, c = s & 63;
                Ws[nn * WSTR + c] = (nn == c && c < NRELC) ? 0x3F800000u : 0u;
            }
        }
        __syncthreads();

        // ---- acc2 += V(128x128) @ Ws(128x64) ----
#pragma unroll
        for (int kk = 0; kk < 16; kk++) {
            unsigned af[4][4], bf[2][2];
#pragma unroll
            for (int tm = 0; tm < 4; tm++) {
                const unsigned* p = Vs + (wr * 64 + tm * 16 + (lane >> 2)) * VSTR + kk * 8 + (lane & 3);
                af[tm][0] = p[0];
                af[tm][1] = p[8 * VSTR];
                af[tm][2] = p[4];
                af[tm][3] = p[8 * VSTR + 4];
            }
#pragma unroll
            for (int tn = 0; tn < 2; tn++) {
                const unsigned* p = Ws + (kk * 8 + (lane & 3)) * WSTR + wc * 16 + tn * 8 + (lane >> 2);
                bf[tn][0] = p[0];
                bf[tn][1] = p[4 * WSTR];
            }
#pragma unroll
            for (int tm = 0; tm < 4; tm++)
#pragma unroll
                for (int tn = 0; tn < 2; tn++)
                    mma8(acc2[tm][tn], af[tm], bf[tn]);
        }
        __syncthreads();
    }

    // ---- epilogue: + b_rel + b_ctx + freq_table[pair_pred] ----
#pragma unroll
    for (int tm = 0; tm < 4; tm++) {
        int rl = wr * 64 + tm * 16 + (lane >> 2);
#pragma unroll
        for (int tn = 0; tn < 2; tn++) {
            int c = wc * 16 + tn * 8 + 2 * (lane & 3);
#pragma unroll
            for (int q = 0; q < 4; q++) {
                int row = rl + ((q >= 2) ? 8 : 0);
                int col = c + (q & 1);
                if (col < NRELC) {
                    float v = acc2[tm][tn][q] + __ldg(brel + col) + __ldg(bctx + col)
                            + __ldg(freq + (size_t)pp[row] * NRELC + col);
                    out[(size_t)(m0 + row) * NRELC + col] = v;
                }
            }
        }
    }
}

// ============================================================================
// Launch
// ============================================================================
extern "C" void kernel_launch(void* const* d_in, const int* in_sizes, int n_in,
                              void* d_out, int out_size) {
    (void)in_sizes; (void)n_in; (void)out_size;
    const float* edge_ctx  = (const float*)d_in[0];
    const int*   obj_preds = (const int*)d_in[1];
    const int*   pair_idx  = (const int*)d_in[2];
    const float* U         = (const float*)d_in[3];
    const float* Wpe       = (const float*)d_in[4];
    const float* bpe       = (const float*)d_in[5];
    const float* Wpc       = (const float*)d_in[6];
    const float* bpc       = (const float*)d_in[7];
    const float* Wrel      = (const float*)d_in[8];
    const float* brel      = (const float*)d_in[9];
    const float* Wctx      = (const float*)d_in[10];
    const float* bctx      = (const float*)d_in[11];
    const float* freq      = (const float*)d_in[12];
    float* out = (float*)d_out;

    cudaFuncSetAttribute(k1_edge_rep, cudaFuncAttributeMaxDynamicSharedMemorySize, K1_SMEM);
    cudaFuncSetAttribute(k2_main,     cudaFuncAttributeMaxDynamicSharedMemorySize, K2_SMEM);

    k1_edge_rep<<<dim3(64, 8), 256, K1_SMEM>>>(edge_ctx, Wpe, bpe);
    k2_main<<<512, 256, K2_SMEM>>>(pair_idx, obj_preds, U, Wpc, bpc,
                                   Wrel, brel, Wctx, bctx, freq, out);
}